// round 4
// baseline (speedup 1.0000x reference)
#include <cuda_runtime.h>
#include <math.h>

#define NC 16
#define MARGIN 0.3f
#define EPS 1e-8f
#define INVALID 0x7fffffff
#define BLOCK 256
#define UNROLL 4

// ---------------- device-global scratch (zero-init on load; reset by finalizer) --
__device__ int      g_present[NC];
__device__ float    g_D[NC * NC];
__device__ float    g_sum_rank;
__device__ float    g_sum_per;
__device__ int      g_cnt;
__device__ unsigned g_ready;   // counts D-row producer blocks that finished
__device__ unsigned g_done;    // counts blocks that finished accumulation

// Dedup-min: within one load slot the global index rises with lane, so the
// lowest-lane peer holding a given class value owns the warp minimum.
__device__ __forceinline__ void first_update(unsigned w, int i, int* s_first) {
    unsigned peers = __match_any_sync(0xffffffffu, w);
    int leader = __ffs(peers) - 1;
    if (((int)(threadIdx.x & 31) == leader) && w < (unsigned)NC)
        atomicMin(&s_first[w], i);
}

__global__ __launch_bounds__(BLOCK) void fused(
    const float* __restrict__ inputs, const void* __restrict__ tm,
    const void* __restrict__ ua, int n_tm, int T, int D,
    int nblocks, float* __restrict__ out)
{
    __shared__ int   s_first[NC];
    __shared__ int   s_ua64, s_tm64;
    __shared__ float sD[NC * NC];          // also reused as cross-warp partials
    __shared__ int   sP[NC];
    __shared__ float srk[BLOCK / 32], spr[BLOCK / 32];
    __shared__ int   sv[BLOCK / 32];

    const int tid = threadIdx.x;
    const int bid = blockIdx.x;
    const bool isD = (bid < NC);           // block-uniform

    if (tid < NC) s_first[tid] = INVALID;
    if (tid == 0) { s_ua64 = 1; s_tm64 = 1; }
    __syncthreads();

    const unsigned* uw = (const unsigned*)ua;
    const unsigned* tw = (const unsigned*)tm;

    // ---- Phase 0: dtype detection. Values in [0,16): int64 => all odd 32-bit
    // words are zero; int32 => odd-index elements are random in [0,16).
    {
        if (tid < 32) {                    // sample ua
            int w = 2 * tid + 1;           // < 64 <= 3*T words guaranteed
            unsigned v = (w < 3 * T) ? uw[w] : 0u;
            if (v) s_ua64 = 0;
        } else if (tid < 64 && isD) {      // sample tm (only producers need it)
            int w = 2 * (tid - 32) + 1;
            unsigned v = (w < n_tm) ? tw[w] : 0u;
            if (v) s_tm64 = 0;
        }
    }
    __syncthreads();

    // ---- Phase 1 (all blocks): front-batch the ua index loads into registers.
    // These DRAM loads fly while the producer blocks build the D table.
    const int ua64 = s_ua64;
    int  c0[UNROLL], c1[UNROLL], c2[UNROLL];
    bool act[UNROLL];
    {
        const int base = bid * BLOCK * UNROLL + tid;
        #pragma unroll
        for (int k = 0; k < UNROLL; k++) {
            int t = base + k * BLOCK;
            act[k] = (t < T);
            c0[k] = c1[k] = c2[k] = 0;
            if (act[k]) {
                if (ua64) {
                    size_t b = (size_t)6 * t;
                    c0[k] = (int)__ldg(uw + b);
                    c1[k] = (int)__ldg(uw + b + 2);
                    c2[k] = (int)__ldg(uw + b + 4);
                } else {
                    size_t b = (size_t)3 * t;
                    c0[k] = (int)__ldg(uw + b);
                    c1[k] = (int)__ldg(uw + b + 1);
                    c2[k] = (int)__ldg(uw + b + 2);
                }
            }
        }
    }

    // ---- Phase 1b (producer blocks): first_idx scan + one distance row.
    if (isD) {
        const int tm64 = s_tm64;
        for (int b0 = 0; b0 < n_tm; b0 += 16 * BLOCK) {
            unsigned wv[16];
            int      ix[16];
            #pragma unroll
            for (int r = 0; r < 16; r++) {
                int i = b0 + r * BLOCK + tid;
                ix[r] = i;
                wv[r] = ~0u;
                if (i < n_tm) wv[r] = tm64 ? tw[2 * i] : tw[i];
            }
            #pragma unroll
            for (int r = 0; r < 16; r++) first_update(wv[r], ix[r], s_first);
        }
        __syncthreads();

        int fj[NC];
        #pragma unroll
        for (int j = 0; j < NC; j++) {
            int f = s_first[j];
            fj[j] = (f == INVALID) ? 0 : f;    // argmax over all-false row == 0
        }
        const int fi = fj[bid];

        float acc[NC];
        #pragma unroll
        for (int j = 0; j < NC; j++) acc[j] = 0.0f;

        for (int b0 = 0; b0 < D; b0 += BLOCK) {
            int k = b0 + tid;
            if (k < D) {
                float x = __ldg(inputs + (size_t)fi * D + k);
                float y[NC];
                #pragma unroll
                for (int j = 0; j < NC; j++)
                    y[j] = __ldg(inputs + (size_t)fj[j] * D + k);
                #pragma unroll
                for (int j = 0; j < NC; j++) {
                    float d = x - y[j];
                    acc[j] = fmaf(d, d, acc[j]);
                }
            }
        }
        #pragma unroll
        for (int j = 0; j < NC; j++) {
            float s = acc[j];
            #pragma unroll
            for (int o = 16; o > 0; o >>= 1) s += __shfl_xor_sync(~0u, s, o);
            acc[j] = s;
        }
        int w = tid >> 5;
        if ((tid & 31) == 0) {
            #pragma unroll
            for (int j = 0; j < NC; j++) sD[w * NC + j] = acc[j];   // reuse sD
        }
        __syncthreads();
        if (tid < NC) {
            float s = 0.0f;
            #pragma unroll
            for (int k = 0; k < BLOCK / 32; k++) s += sD[k * NC + tid];
            g_D[bid * NC + tid] = sqrtf(fmaxf(s, 1e-12f));
            g_present[tid] = (s_first[tid] != INVALID) ? 1 : 0;   // identical dups
        }
        __syncthreads();
        __threadfence();
        if (tid == 0) atomicAdd(&g_ready, 1u);
    }

    // ---- Phase 2 (all blocks): wait for the table, stage it in smem.
    if (tid == 0) {
        while (atomicAdd(&g_ready, 0u) < (unsigned)NC) { }
    }
    __syncthreads();
    sD[tid] = __ldcg(&g_D[tid]);                     // BLOCK == NC*NC
    if (tid < NC) sP[tid] = __ldcg(&g_present[tid]);
    __syncthreads();

    // ---- Phase 3: per-triple losses + reduction.
    float rk = 0.0f, pr = 0.0f;
    int v = 0;
    #pragma unroll
    for (int k = 0; k < UNROLL; k++) {
        if (act[k]) {
            int a = c0[k], p = c1[k], n = c2[k];
            bool ok = ((unsigned)a < 16u) & ((unsigned)p < 16u) & ((unsigned)n < 16u);
            if (ok && sP[a] && sP[p] && sP[n]) {
                v++;
                float dap = sD[a * NC + p];
                float dan = sD[a * NC + n];
                rk += fmaxf(dap - dan + MARGIN, 0.0f);
                // s_ap/(s_ap+s_an) with s=1/(d+1)  ==  (dan+1)/(dap+dan+2)
                float p_ap = __fdividef(dan + 1.0f, dap + dan + 2.0f);
                pr -= __logf(p_ap + EPS);
            }
        }
    }
    #pragma unroll
    for (int o = 16; o > 0; o >>= 1) {
        rk += __shfl_xor_sync(~0u, rk, o);
        pr += __shfl_xor_sync(~0u, pr, o);
        v  += __shfl_xor_sync(~0u, v,  o);
    }
    int w = tid >> 5;
    if ((tid & 31) == 0) { srk[w] = rk; spr[w] = pr; sv[w] = v; }
    __syncthreads();

    if (tid == 0) {
        float R = 0.0f, P = 0.0f; int V = 0;
        #pragma unroll
        for (int k = 0; k < BLOCK / 32; k++) { R += srk[k]; P += spr[k]; V += sv[k]; }
        atomicAdd(&g_sum_rank, R);
        atomicAdd(&g_sum_per,  P);
        atomicAdd(&g_cnt,      V);
        __threadfence();
        unsigned d = atomicAdd(&g_done, 1u);
        if (d == (unsigned)(nblocks - 1)) {
            float sr  = atomicAdd(&g_sum_rank, 0.0f);
            float sp2 = atomicAdd(&g_sum_per,  0.0f);
            int   cn  = atomicAdd(&g_cnt,      0);
            float nv = fmaxf((float)cn, 1.0f);
            float lh = sr / nv;
            float lp = sp2 / nv;
            out[0] = lh + lp;
            out[1] = lh;
            out[2] = lp;
            // reset for the next (graph-replayed) launch
            g_sum_rank = 0.0f; g_sum_per = 0.0f; g_cnt = 0;
            g_done = 0u; g_ready = 0u;
        }
    }
}

// ---------------- launch ----------------
// Inputs: 0 preds_mat(f32), 1 preds_sub(f32), 2 inputs(f32 B*D),
// 3 targets_mat(int, B), 4 targets_sub(int, B), 5 user_answers(int, T*3)
extern "C" void kernel_launch(void* const* d_in, const int* in_sizes, int n_in,
                              void* d_out, int out_size) {
    const float* inputs = (const float*)d_in[2];
    const void*  tm     = d_in[3];
    const void*  ua     = d_in[5];
    int n_tm = in_sizes[3];
    int T    = in_sizes[5] / 3;
    int D    = in_sizes[2] / n_tm;

    int nb = (T + BLOCK * UNROLL - 1) / (BLOCK * UNROLL);
    if (nb < NC) nb = NC;
    fused<<<nb, BLOCK>>>(inputs, tm, ua, n_tm, T, D, nb, (float*)d_out);
}

// round 5
// speedup vs baseline: 1.5584x; 1.5584x over previous
#include <cuda_runtime.h>
#include <math.h>

#define NUM_CLASSES 16
#define MARGIN 0.3f
#define EPS 1e-8f
#define INVALID 0x7fffffff

// ---------------- device-global scratch (no allocations allowed) ----------------
__device__ int   g_first_idx[NUM_CLASSES];
__device__ int   g_present[NUM_CLASSES];
__device__ int   g_ua64;          // 1 if user_answers is int64, 0 if int32
__device__ float g_D[NUM_CLASSES * NUM_CLASSES];
__device__ float g_S[NUM_CLASSES * NUM_CLASSES];
__device__ float g_sum_rank;
__device__ float g_sum_per;
__device__ int   g_cnt;
__device__ unsigned g_done;

// Dedup-min: within one load slot the global index rises with lane, so the
// lowest-lane peer holding a given class value owns the warp minimum.
__device__ __forceinline__ void first_update(unsigned w, int i, int* s_first) {
    unsigned peers = __match_any_sync(0xffffffffu, w);
    int leader = __ffs(peers) - 1;
    if (((int)(threadIdx.x & 31) == leader) && w < (unsigned)NUM_CLASSES)
        atomicMin(&s_first[w], i);
}

// ---------------- K1: dtype detection + first_idx + accumulator reset ----------------
// Single block, 1024 threads. ALL loads for the common case are issued in one
// front batch (detection samples + int32-interpretation scan + the first half
// of the int64 interpretation, which is in-bounds under either dtype). Only
// the unlikely int64 case pays a second DRAM round-trip (for its upper half).
__global__ __launch_bounds__(1024) void k1_prep(const void* __restrict__ tm,
                                                const void* __restrict__ ua,
                                                int n_tm, int n_ua_elems) {
    __shared__ int s_first[NUM_CLASSES];
    __shared__ int s_tm_nz, s_ua_nz;
    const int tid = threadIdx.x;

    if (tid < NUM_CLASSES) s_first[tid] = INVALID;
    if (tid == 0) { s_tm_nz = 0; s_ua_nz = 0; }
    __syncthreads();

    const unsigned* tw = (const unsigned*)tm;
    const unsigned* uw = (const unsigned*)ua;

    // ---- front batch: everything independent, issued before any consumption.
    // detection samples (odd words; int64 => all zero since values < 16)
    unsigned dt = 0u, du = 0u;
    {
        int w0 = 2 * tid + 1;                 // odd word
        if (w0 < n_tm)       dt = tw[w0];     // n_tm words exist at minimum
        int w1 = w0 + 2048;
        if (w1 < n_tm)       dt |= tw[w1];
        if (w0 < n_ua_elems) du = uw[w0];
        int w2 = w0 + 2048;
        if (w2 < n_ua_elems) du |= uw[w2];
    }
    // int32-interpretation scan loads (cover i < min(n_tm, 4096))
    unsigned w32[4]; int i32x[4];
    #pragma unroll
    for (int r = 0; r < 4; r++) {
        int i = r * 1024 + tid;
        i32x[r] = i;
        w32[r] = (i < n_tm) ? tw[i] : ~0u;
    }
    // int64-interpretation first-half loads: word 2*i < n_tm is in-bounds
    // under either dtype (n_tm 32-bit words always exist).
    unsigned w64lo[2]; int i64x[2];
    #pragma unroll
    for (int r = 0; r < 2; r++) {
        int i = r * 1024 + tid;
        i64x[r] = i;
        w64lo[r] = (2 * i < n_tm && i < n_tm) ? tw[2 * i] : ~0u;
    }

    if (dt) s_tm_nz = 1;
    if (du) s_ua_nz = 1;
    __syncthreads();
    const int tm64 = (s_tm_nz == 0);

    // ---- dedup'd first-occurrence update, fast path n_tm <= 4096
    if (!tm64) {
        #pragma unroll
        for (int r = 0; r < 4; r++) first_update(w32[r], i32x[r], s_first);
        // tail for n_tm > 4096
        for (int i = 4096 + tid; i < n_tm; i += 1024)
            first_update(tw[i], i, s_first);
    } else {
        #pragma unroll
        for (int r = 0; r < 2; r++) first_update(w64lo[r], i64x[r], s_first);
        // upper half (only reachable when dtype really is int64 => 2*n_tm words)
        for (int i = 2048 + tid; i < n_tm; i += 1024)
            first_update(tw[2 * i], i, s_first);
    }
    __syncthreads();

    if (tid < NUM_CLASSES) {
        int f = s_first[tid];
        g_present[tid]   = (f != INVALID) ? 1 : 0;
        g_first_idx[tid] = (f == INVALID) ? 0 : f;   // argmax of all-false row == 0
    }
    if (tid == 0) {
        g_ua64 = (s_ua_nz == 0) ? 1 : 0;
        g_sum_rank = 0.0f;
        g_sum_per  = 0.0f;
        g_cnt  = 0;
        g_done = 0u;
    }
}

// ---------------- K2: 16x16 distance table (identical to R2) ----------------
__global__ void k2_dist(const float* __restrict__ inputs, int D) {
    int i = blockIdx.x >> 4;
    int j = blockIdx.x & 15;
    int fi = g_first_idx[i];
    int fj = g_first_idx[j];
    const float4* a = (const float4*)(inputs + (size_t)fi * D);
    const float4* b = (const float4*)(inputs + (size_t)fj * D);
    int nvec = D >> 2;

    float s = 0.0f;
    for (int k = threadIdx.x; k < nvec; k += blockDim.x) {
        float4 x = __ldg(a + k);
        float4 y = __ldg(b + k);
        float d0 = x.x - y.x, d1 = x.y - y.y, d2 = x.z - y.z, d3 = x.w - y.w;
        s = fmaf(d0, d0, s); s = fmaf(d1, d1, s);
        s = fmaf(d2, d2, s); s = fmaf(d3, d3, s);
    }
    #pragma unroll
    for (int o = 16; o > 0; o >>= 1) s += __shfl_xor_sync(0xffffffffu, s, o);

    __shared__ float sp[4];
    if ((threadIdx.x & 31) == 0) sp[threadIdx.x >> 5] = s;
    __syncthreads();
    if (threadIdx.x == 0) {
        float d2sum = sp[0] + sp[1] + sp[2] + sp[3];
        d2sum = fmaxf(d2sum, 1e-12f);
        float d = sqrtf(d2sum);
        g_D[blockIdx.x] = d;
        g_S[blockIdx.x] = 1.0f / (d + 1.0f);
    }
}

// ---------------- K3: main reduction over T triples (identical to R2) ----------------
__global__ void k3_main(const void* __restrict__ ua, int T, int nblocks,
                        float* __restrict__ out) {
    int t = blockIdx.x * blockDim.x + threadIdx.x;
    float rk = 0.0f, pr = 0.0f;
    int v = 0;

    if (t < T) {
        int c0, c1, c2;
        if (g_ua64) {
            const long long* p = (const long long*)ua + (size_t)3 * t;
            c0 = (int)__ldg(p); c1 = (int)__ldg(p+1); c2 = (int)__ldg(p+2);
        } else {
            const int* p = (const int*)ua + (size_t)3 * t;
            c0 = __ldg(p); c1 = __ldg(p+1); c2 = __ldg(p+2);
        }
        bool inrange = ((unsigned)c0 < 16u) & ((unsigned)c1 < 16u) & ((unsigned)c2 < 16u);
        if (inrange && g_present[c0] && g_present[c1] && g_present[c2]) {
            v = 1;
            int iap = c0 * 16 + c1;
            int ian = c0 * 16 + c2;
            float dap = __ldg(&g_D[iap]);
            float dan = __ldg(&g_D[ian]);
            rk = fmaxf(dap - dan + MARGIN, 0.0f);
            float sap = __ldg(&g_S[iap]);
            float san = __ldg(&g_S[ian]);
            pr = -logf(sap / (sap + san) + EPS);
        }
    }

    #pragma unroll
    for (int o = 16; o > 0; o >>= 1) {
        rk += __shfl_xor_sync(0xffffffffu, rk, o);
        pr += __shfl_xor_sync(0xffffffffu, pr, o);
        v  += __shfl_xor_sync(0xffffffffu, v,  o);
    }

    __shared__ float srk[8], spr[8];
    __shared__ int   sv[8];
    int w = threadIdx.x >> 5;
    if ((threadIdx.x & 31) == 0) { srk[w] = rk; spr[w] = pr; sv[w] = v; }
    __syncthreads();

    if (threadIdx.x == 0) {
        float R = 0.0f, P = 0.0f; int V = 0;
        int nw = blockDim.x >> 5;
        for (int k = 0; k < nw; k++) { R += srk[k]; P += spr[k]; V += sv[k]; }
        atomicAdd(&g_sum_rank, R);
        atomicAdd(&g_sum_per,  P);
        atomicAdd(&g_cnt,      V);
        __threadfence();
        unsigned d = atomicAdd(&g_done, 1u);
        if (d == (unsigned)(nblocks - 1)) {
            float sr = atomicAdd(&g_sum_rank, 0.0f);
            float sp2 = atomicAdd(&g_sum_per, 0.0f);
            int   cn = atomicAdd(&g_cnt, 0);
            float nv = fmaxf((float)cn, 1.0f);
            float lh = sr / nv;
            float lp = sp2 / nv;
            out[0] = lh + lp;
            out[1] = lh;
            out[2] = lp;
        }
    }
}

// ---------------- launch ----------------
// Inputs: 0 preds_mat(f32), 1 preds_sub(f32), 2 inputs(f32 B*D),
// 3 targets_mat(int, B), 4 targets_sub(int, B), 5 user_answers(int, T*3)
extern "C" void kernel_launch(void* const* d_in, const int* in_sizes, int n_in,
                              void* d_out, int out_size) {
    const float* inputs = (const float*)d_in[2];
    const void*  tm     = d_in[3];
    const void*  ua     = d_in[5];
    int n_tm = in_sizes[3];
    int n_ua = in_sizes[5];
    int T = n_ua / 3;
    int D = in_sizes[2] / n_tm;

    k1_prep<<<1, 1024>>>(tm, ua, n_tm, n_ua);
    k2_dist<<<NUM_CLASSES * NUM_CLASSES, 128>>>(inputs, D);
    int nb = (T + 255) / 256;
    k3_main<<<nb, 256>>>(ua, T, nb, (float*)d_out);
}

// round 6
// speedup vs baseline: 1.6364x; 1.0500x over previous
#include <cuda_runtime.h>
#include <math.h>

#define NC 16
#define MARGIN 0.3f
#define EPS 1e-8f
#define INVALID 0x7fffffff

// ---------------- device-global scratch (zero-init; kB finalizer resets) -------
__device__ float    g_D[NC * NC];
__device__ int      g_present[NC];
__device__ float    g_sum_rank;
__device__ float    g_sum_per;
__device__ int      g_cnt;
__device__ unsigned g_done;

// Dedup-min: within one load slot the global index rises with lane, so the
// lowest-lane peer holding a given class value owns the warp minimum.
__device__ __forceinline__ void first_update(unsigned w, int i, int* s_first) {
    unsigned peers = __match_any_sync(0xffffffffu, w);
    int leader = __ffs(peers) - 1;
    if (((int)(threadIdx.x & 31) == leader) && w < (unsigned)NC)
        atomicMin(&s_first[w], i);
}

// ---------------- kA: 120 blocks, each = redundant first_idx scan + ONE pair ----
// Pair (i<j) from triangular block index; D symmetric, diag = 1e-6 exactly
// matches sqrt(clip(0, 1e-12)).
__global__ __launch_bounds__(256) void kA(const float* __restrict__ inputs,
                                          const void* __restrict__ tm,
                                          int n_tm, int D) {
    __shared__ int   s_first[NC];
    __shared__ int   s_nz;
    __shared__ float s_part[8];
    const int tid = threadIdx.x;

    if (tid < NC) s_first[tid] = INVALID;
    if (tid == 0) s_nz = 0;
    __syncthreads();

    const unsigned* tw = (const unsigned*)tm;

    // -- front batch: dtype samples + int32-interpretation scan loads.
    // Values in [0,16): if int64, every odd 32-bit word is 0.
    unsigned det = 0u;
    {
        int w0 = 2 * tid + 1;           // n_tm words exist at minimum
        if (w0 < n_tm) det = tw[w0];
        int w1 = w0 + 512;
        if (w1 < n_tm) det |= tw[w1];
    }
    unsigned wv[16];
    #pragma unroll
    for (int r = 0; r < 16; r++) {
        int i = r * 256 + tid;
        wv[r] = (i < n_tm) ? tw[i] : ~0u;
    }
    if (det) s_nz = 1;
    __syncthreads();

    if (s_nz) {  // int32: speculative loads are the real data
        #pragma unroll
        for (int r = 0; r < 16; r++) first_update(wv[r], r * 256 + tid, s_first);
        for (int i = 4096 + tid; i < n_tm; i += 256)
            first_update(tw[i], i, s_first);
    } else {     // int64: low words at stride 2 (buffer has 2*n_tm words)
        for (int i = tid; i < n_tm; i += 256)
            first_update(tw[2 * i], i, s_first);
    }
    __syncthreads();

    // -- pair (i, j), i < j, from triangular index
    int b = blockIdx.x, pi = 0, rem = b, cnt = NC - 1;
    while (rem >= cnt) { rem -= cnt; cnt--; pi++; }
    int pj = pi + 1 + rem;

    int fi = s_first[pi]; if (fi == INVALID) fi = 0;   // argmax all-false == 0
    int fj = s_first[pj]; if (fj == INVALID) fj = 0;

    // -- squared distance, 4 floats per thread per 1024-float stripe
    float acc = 0.0f;
    const float* ra = inputs + (size_t)fi * D;
    const float* rb = inputs + (size_t)fj * D;
    for (int base = 0; base < D; base += 1024) {
        int k = base + tid * 4;
        if (k + 4 <= D) {
            float4 x = __ldg((const float4*)(ra + k));
            float4 y = __ldg((const float4*)(rb + k));
            float d0 = x.x - y.x, d1 = x.y - y.y, d2 = x.z - y.z, d3 = x.w - y.w;
            acc = fmaf(d0, d0, acc); acc = fmaf(d1, d1, acc);
            acc = fmaf(d2, d2, acc); acc = fmaf(d3, d3, acc);
        } else {
            for (int q = k; q < D && q < k + 4; q++) {
                float d = __ldg(ra + q) - __ldg(rb + q);
                acc = fmaf(d, d, acc);
            }
        }
    }
    #pragma unroll
    for (int o = 16; o > 0; o >>= 1) acc += __shfl_xor_sync(~0u, acc, o);
    if ((tid & 31) == 0) s_part[tid >> 5] = acc;
    __syncthreads();

    if (tid == 0) {
        float s = 0.0f;
        #pragma unroll
        for (int k = 0; k < 8; k++) s += s_part[k];
        float d = sqrtf(fmaxf(s, 1e-12f));
        g_D[pi * NC + pj] = d;
        g_D[pj * NC + pi] = d;
    }
    if (blockIdx.x == 0 && tid < NC) {
        g_D[tid * NC + tid] = 1e-6f;                       // sqrt(1e-12)
        g_present[tid] = (s_first[tid] != INVALID) ? 1 : 0;
    }
}

// ---------------- kB: 32 blocks x 1024 thr x 4 triples ----------------
__global__ __launch_bounds__(1024) void kB(const void* __restrict__ ua, int T,
                                           float* __restrict__ out) {
    __shared__ float sD[NC * NC];
    __shared__ int   sP[NC];
    __shared__ int   s_nz;
    __shared__ float srk[32], spr[32];
    __shared__ int   sv[32];

    const int tid = threadIdx.x;
    const int bid = blockIdx.x;
    if (tid == 0) s_nz = 0;

    const unsigned* uw = (const unsigned*)ua;

    // -- front batch: dtype sample + table + vectorized int32-interp ua loads.
    unsigned det = uw[2 * tid + 1];            // < 2048 < 3T words: always safe
    float dval = (tid < NC * NC) ? __ldcg(&g_D[tid]) : 0.0f;
    int   pval = (tid < NC) ? __ldcg(&g_present[tid]) : 0;

    const int t0 = (bid * 1024 + tid) * 4;     // first of 4 triples
    int4 q0, q1, q2;
    const bool vec_ok = (t0 + 4 <= T);         // words 3*t0 .. 3*t0+11 < 3T
    if (vec_ok) {                              // 12*t0 bytes, 16B aligned
        const int4* p = (const int4*)(uw + 3 * (size_t)t0);
        q0 = __ldg(p); q1 = __ldg(p + 1); q2 = __ldg(p + 2);
    }

    if (det) s_nz = 1;
    if (tid < NC * NC) sD[tid] = dval;
    if (tid < NC) sP[tid] = pval;
    __syncthreads();
    const int ua64 = (s_nz == 0);

    // -- gather the 12 indices for this thread's 4 triples
    int c[4][3];
    if (!ua64 && vec_ok) {
        c[0][0]=q0.x; c[0][1]=q0.y; c[0][2]=q0.z;
        c[1][0]=q0.w; c[1][1]=q1.x; c[1][2]=q1.y;
        c[2][0]=q1.z; c[2][1]=q1.w; c[2][2]=q2.x;
        c[3][0]=q2.y; c[3][1]=q2.z; c[3][2]=q2.w;
    } else {
        #pragma unroll
        for (int k = 0; k < 4; k++) {
            int t = t0 + k;
            c[k][0] = c[k][1] = c[k][2] = -1;
            if (t < T) {
                if (ua64) {
                    size_t b = (size_t)6 * t;
                    c[k][0] = (int)__ldg(uw + b);
                    c[k][1] = (int)__ldg(uw + b + 2);
                    c[k][2] = (int)__ldg(uw + b + 4);
                } else {
                    size_t b = (size_t)3 * t;
                    c[k][0] = (int)__ldg(uw + b);
                    c[k][1] = (int)__ldg(uw + b + 1);
                    c[k][2] = (int)__ldg(uw + b + 2);
                }
            }
        }
    }

    // -- per-triple losses
    float rk = 0.0f, pr = 0.0f;
    int v = 0;
    #pragma unroll
    for (int k = 0; k < 4; k++) {
        int a = c[k][0], p = c[k][1], n = c[k][2];
        if ((t0 + k) < T) {
            bool ok = ((unsigned)a < 16u) & ((unsigned)p < 16u) & ((unsigned)n < 16u);
            if (ok && sP[a] && sP[p] && sP[n]) {
                v++;
                float dap = sD[a * NC + p];
                float dan = sD[a * NC + n];
                rk += fmaxf(dap - dan + MARGIN, 0.0f);
                // 1/(d+1) similarity:  p_ap = (dan+1)/(dap+dan+2)
                float p_ap = __fdividef(dan + 1.0f, dap + dan + 2.0f);
                pr -= __logf(p_ap + EPS);
            }
        }
    }
    // grid-stride tail (only if T > 131072)
    for (int t = gridDim.x * 1024 * 4 + bid * 1024 + tid; t < T;
         t += gridDim.x * 1024) {
        int a, p, n;
        if (ua64) {
            size_t b = (size_t)6 * t;
            a = (int)__ldg(uw + b); p = (int)__ldg(uw + b + 2); n = (int)__ldg(uw + b + 4);
        } else {
            size_t b = (size_t)3 * t;
            a = (int)__ldg(uw + b); p = (int)__ldg(uw + b + 1); n = (int)__ldg(uw + b + 2);
        }
        bool ok = ((unsigned)a < 16u) & ((unsigned)p < 16u) & ((unsigned)n < 16u);
        if (ok && sP[a] && sP[p] && sP[n]) {
            v++;
            float dap = sD[a * NC + p];
            float dan = sD[a * NC + n];
            rk += fmaxf(dap - dan + MARGIN, 0.0f);
            float p_ap = __fdividef(dan + 1.0f, dap + dan + 2.0f);
            pr -= __logf(p_ap + EPS);
        }
    }

    #pragma unroll
    for (int o = 16; o > 0; o >>= 1) {
        rk += __shfl_xor_sync(~0u, rk, o);
        pr += __shfl_xor_sync(~0u, pr, o);
        v  += __shfl_xor_sync(~0u, v,  o);
    }
    int w = tid >> 5;
    if ((tid & 31) == 0) { srk[w] = rk; spr[w] = pr; sv[w] = v; }
    __syncthreads();

    if (tid == 0) {
        float R = 0.0f, P = 0.0f; int V = 0;
        #pragma unroll
        for (int k = 0; k < 32; k++) { R += srk[k]; P += spr[k]; V += sv[k]; }
        atomicAdd(&g_sum_rank, R);
        atomicAdd(&g_sum_per,  P);
        atomicAdd(&g_cnt,      V);
        __threadfence();
        unsigned d = atomicAdd(&g_done, 1u);
        if (d == gridDim.x - 1) {
            float sr  = atomicAdd(&g_sum_rank, 0.0f);
            float sp2 = atomicAdd(&g_sum_per,  0.0f);
            int   cn  = atomicAdd(&g_cnt,      0);
            float nv = fmaxf((float)cn, 1.0f);
            float lh = sr / nv;
            float lp = sp2 / nv;
            out[0] = lh + lp;
            out[1] = lh;
            out[2] = lp;
            // reset for graph replay
            g_sum_rank = 0.0f; g_sum_per = 0.0f; g_cnt = 0; g_done = 0u;
        }
    }
}

// ---------------- launch ----------------
// Inputs: 0 preds_mat(f32), 1 preds_sub(f32), 2 inputs(f32 B*D),
// 3 targets_mat(int, B), 4 targets_sub(int, B), 5 user_answers(int, T*3)
extern "C" void kernel_launch(void* const* d_in, const int* in_sizes, int n_in,
                              void* d_out, int out_size) {
    const float* inputs = (const float*)d_in[2];
    const void*  tm     = d_in[3];
    const void*  ua     = d_in[5];
    int n_tm = in_sizes[3];
    int T    = in_sizes[5] / 3;
    int D    = in_sizes[2] / n_tm;

    kA<<<(NC * (NC - 1)) / 2, 256>>>(inputs, tm, n_tm, D);   // 120 blocks
    kB<<<32, 1024>>>(ua, T, (float*)d_out);
}

// round 7
// speedup vs baseline: 1.8653x; 1.1399x over previous
#include <cuda_runtime.h>
#include <math.h>

#define NC 16
#define MARGIN 0.3f
#define INVALID 0x7fffffff

// ---------------- device-global scratch (zero-init; kB finalizer resets) -------
__device__ float    g_D[NC * NC];
__device__ int      g_present[NC];
__device__ float    g_sum_rank;
__device__ float    g_sum_per;
__device__ int      g_cnt;
__device__ unsigned g_done;

// Dedup-min: within one load slot the global index rises with lane, so the
// lowest-lane peer holding a given class value owns the warp minimum.
__device__ __forceinline__ void first_update(unsigned w, int i, int* s_first) {
    unsigned peers = __match_any_sync(0xffffffffu, w);
    int leader = __ffs(peers) - 1;
    if (((int)(threadIdx.x & 31) == leader) && w < (unsigned)NC)
        atomicMin(&s_first[w], i);
}

// ---------------- kA: 120 blocks, each = redundant first_idx scan + ONE pair ----
__global__ __launch_bounds__(256) void kA(const float* __restrict__ inputs,
                                          const void* __restrict__ tm,
                                          int n_tm, int D) {
    __shared__ int   s_first[NC];
    __shared__ int   s_nz;
    __shared__ float s_part[8];
    const int tid = threadIdx.x;

    if (tid < NC) s_first[tid] = INVALID;
    if (tid == 0) s_nz = 0;
    __syncthreads();

    const unsigned* tw = (const unsigned*)tm;

    // front batch: dtype samples + int32-interpretation scan loads.
    unsigned det = 0u;
    {
        int w0 = 2 * tid + 1;
        if (w0 < n_tm) det = tw[w0];
        int w1 = w0 + 512;
        if (w1 < n_tm) det |= tw[w1];
    }
    unsigned wv[16];
    #pragma unroll
    for (int r = 0; r < 16; r++) {
        int i = r * 256 + tid;
        wv[r] = (i < n_tm) ? tw[i] : ~0u;
    }
    if (det) s_nz = 1;
    __syncthreads();

    if (s_nz) {  // int32
        #pragma unroll
        for (int r = 0; r < 16; r++) first_update(wv[r], r * 256 + tid, s_first);
        for (int i = 4096 + tid; i < n_tm; i += 256)
            first_update(tw[i], i, s_first);
    } else {     // int64: low words at stride 2
        for (int i = tid; i < n_tm; i += 256)
            first_update(tw[2 * i], i, s_first);
    }
    __syncthreads();

    // pair (i, j), i < j, from triangular block index
    int b = blockIdx.x, pi = 0, rem = b, cnt = NC - 1;
    while (rem >= cnt) { rem -= cnt; cnt--; pi++; }
    int pj = pi + 1 + rem;

    int fi = s_first[pi]; if (fi == INVALID) fi = 0;
    int fj = s_first[pj]; if (fj == INVALID) fj = 0;

    float acc = 0.0f;
    const float* ra = inputs + (size_t)fi * D;
    const float* rb = inputs + (size_t)fj * D;
    for (int base = 0; base < D; base += 1024) {
        int k = base + tid * 4;
        if (k + 4 <= D) {
            float4 x = __ldg((const float4*)(ra + k));
            float4 y = __ldg((const float4*)(rb + k));
            float d0 = x.x - y.x, d1 = x.y - y.y, d2 = x.z - y.z, d3 = x.w - y.w;
            acc = fmaf(d0, d0, acc); acc = fmaf(d1, d1, acc);
            acc = fmaf(d2, d2, acc); acc = fmaf(d3, d3, acc);
        } else {
            for (int q = k; q < D && q < k + 4; q++) {
                float d = __ldg(ra + q) - __ldg(rb + q);
                acc = fmaf(d, d, acc);
            }
        }
    }
    #pragma unroll
    for (int o = 16; o > 0; o >>= 1) acc += __shfl_xor_sync(~0u, acc, o);
    if ((tid & 31) == 0) s_part[tid >> 5] = acc;
    __syncthreads();

    if (tid == 0) {
        float s = 0.0f;
        #pragma unroll
        for (int k = 0; k < 8; k++) s += s_part[k];
        float d = sqrtf(fmaxf(s, 1e-12f));
        g_D[pi * NC + pj] = d;
        g_D[pj * NC + pi] = d;
    }
    if (blockIdx.x == 0 && tid < NC) {
        g_D[tid * NC + tid] = 1e-6f;                       // sqrt(1e-12)
        g_present[tid] = (s_first[tid] != INVALID) ? 1 : 0;
    }
}

// ---------------- kB: 128 blocks x 256 thr x 4 triples, 1 MUFU/triple ----------
__global__ __launch_bounds__(256) void kB(const void* __restrict__ ua, int T,
                                          float* __restrict__ out) {
    __shared__ float sD[NC * NC];
    __shared__ float sL1[NC * NC];        // log(d + 1) per pair
    __shared__ int   sP[NC];
    __shared__ int   s_nz;
    __shared__ float srk[8], spr[8];
    __shared__ int   sv[8];

    const int tid = threadIdx.x;
    const int bid = blockIdx.x;
    if (tid == 0) s_nz = 0;

    const unsigned* uw = (const unsigned*)ua;

    // -- front batch: dtype sample + table load + vectorized int32-interp loads.
    unsigned det = uw[2 * tid + 1];           // word < 512 < 3T: safe
    float dval = __ldcg(&g_D[tid]);           // 256 threads, 256 entries
    int   pval = (tid < NC) ? __ldcg(&g_present[tid]) : 0;

    const int t0 = (bid * 256 + tid) * 4;
    int4 q0, q1, q2;
    const bool vec_ok = (t0 + 4 <= T);
    if (vec_ok) {
        const int4* p = (const int4*)(uw + 3 * (size_t)t0);
        q0 = __ldg(p); q1 = __ldg(p + 1); q2 = __ldg(p + 2);
    }

    if (det) s_nz = 1;
    sD[tid]  = dval;
    sL1[tid] = __logf(dval + 1.0f);           // 1 MUFU per thread, once
    if (tid < NC) sP[tid] = pval;
    __syncthreads();
    const int ua64 = (s_nz == 0);

    // -- 12 indices for this thread's 4 triples
    int c[4][3];
    if (!ua64 && vec_ok) {
        c[0][0]=q0.x; c[0][1]=q0.y; c[0][2]=q0.z;
        c[1][0]=q0.w; c[1][1]=q1.x; c[1][2]=q1.y;
        c[2][0]=q1.z; c[2][1]=q1.w; c[2][2]=q2.x;
        c[3][0]=q2.y; c[3][1]=q2.z; c[3][2]=q2.w;
    } else {
        #pragma unroll
        for (int k = 0; k < 4; k++) {
            int t = t0 + k;
            c[k][0] = c[k][1] = c[k][2] = -1;
            if (t < T) {
                if (ua64) {
                    size_t b = (size_t)6 * t;
                    c[k][0] = (int)__ldg(uw + b);
                    c[k][1] = (int)__ldg(uw + b + 2);
                    c[k][2] = (int)__ldg(uw + b + 4);
                } else {
                    size_t b = (size_t)3 * t;
                    c[k][0] = (int)__ldg(uw + b);
                    c[k][1] = (int)__ldg(uw + b + 1);
                    c[k][2] = (int)__ldg(uw + b + 2);
                }
            }
        }
    }

    // -- per-triple losses: hinge (FMA only) + perplexity (1 lg2 per triple).
    //    -log(p_ap + EPS) ~= log(dap+dan+2) - log(dan+1)   (EPS ~ 1e-8 << p_ap)
    float rk = 0.0f, pr = 0.0f;
    int v = 0;
    #pragma unroll
    for (int k = 0; k < 4; k++) {
        int a = c[k][0], p = c[k][1], n = c[k][2];
        if ((t0 + k) < T) {
            bool ok = ((unsigned)a < 16u) & ((unsigned)p < 16u) & ((unsigned)n < 16u);
            if (ok && sP[a] && sP[p] && sP[n]) {
                v++;
                float dap = sD[a * NC + p];
                int   ian = a * NC + n;
                float dan = sD[ian];
                rk += fmaxf(dap - dan + MARGIN, 0.0f);
                pr += __logf(dap + dan + 2.0f) - sL1[ian];
            }
        }
    }
    // grid-stride tail (only if T > 131072)
    for (int t = gridDim.x * 256 * 4 + bid * 256 + tid; t < T;
         t += gridDim.x * 256) {
        int a, p, n;
        if (ua64) {
            size_t b = (size_t)6 * t;
            a = (int)__ldg(uw + b); p = (int)__ldg(uw + b + 2); n = (int)__ldg(uw + b + 4);
        } else {
            size_t b = (size_t)3 * t;
            a = (int)__ldg(uw + b); p = (int)__ldg(uw + b + 1); n = (int)__ldg(uw + b + 2);
        }
        bool ok = ((unsigned)a < 16u) & ((unsigned)p < 16u) & ((unsigned)n < 16u);
        if (ok && sP[a] && sP[p] && sP[n]) {
            v++;
            float dap = sD[a * NC + p];
            int   ian = a * NC + n;
            float dan = sD[ian];
            rk += fmaxf(dap - dan + MARGIN, 0.0f);
            pr += __logf(dap + dan + 2.0f) - sL1[ian];
        }
    }

    #pragma unroll
    for (int o = 16; o > 0; o >>= 1) {
        rk += __shfl_xor_sync(~0u, rk, o);
        pr += __shfl_xor_sync(~0u, pr, o);
        v  += __shfl_xor_sync(~0u, v,  o);
    }
    int w = tid >> 5;
    if ((tid & 31) == 0) { srk[w] = rk; spr[w] = pr; sv[w] = v; }
    __syncthreads();

    if (tid == 0) {
        float R = 0.0f, P = 0.0f; int V = 0;
        #pragma unroll
        for (int k = 0; k < 8; k++) { R += srk[k]; P += spr[k]; V += sv[k]; }
        atomicAdd(&g_sum_rank, R);
        atomicAdd(&g_sum_per,  P);
        atomicAdd(&g_cnt,      V);
        __threadfence();
        unsigned d = atomicAdd(&g_done, 1u);
        if (d == gridDim.x - 1) {
            float sr  = atomicAdd(&g_sum_rank, 0.0f);
            float sp2 = atomicAdd(&g_sum_per,  0.0f);
            int   cn  = atomicAdd(&g_cnt,      0);
            float nv = fmaxf((float)cn, 1.0f);
            float lh = sr / nv;
            float lp = sp2 / nv;
            out[0] = lh + lp;
            out[1] = lh;
            out[2] = lp;
            // reset for graph replay
            g_sum_rank = 0.0f; g_sum_per = 0.0f; g_cnt = 0; g_done = 0u;
        }
    }
}

// ---------------- launch ----------------
// Inputs: 0 preds_mat(f32), 1 preds_sub(f32), 2 inputs(f32 B*D),
// 3 targets_mat(int, B), 4 targets_sub(int, B), 5 user_answers(int, T*3)
extern "C" void kernel_launch(void* const* d_in, const int* in_sizes, int n_in,
                              void* d_out, int out_size) {
    const float* inputs = (const float*)d_in[2];
    const void*  tm     = d_in[3];
    const void*  ua     = d_in[5];
    int n_tm = in_sizes[3];
    int T    = in_sizes[5] / 3;
    int D    = in_sizes[2] / n_tm;

    kA<<<(NC * (NC - 1)) / 2, 256>>>(inputs, tm, n_tm, D);   // 120 blocks

    int nb = (T + 256 * 4 - 1) / (256 * 4);
    if (nb > 148) nb = 148;          // single wave; grid-stride tail covers rest
    if (nb < 1) nb = 1;
    kB<<<nb, 256>>>(ua, T, (float*)d_out);
}